// round 4
// baseline (speedup 1.0000x reference)
#include <cuda_runtime.h>
#include <cuda_bf16.h>
#include <cstdint>

// N = 400 nodes, E = N*(N-1) = 159600 edges, B = 32 batch.
// Output [B, E, 2] f32: out[b,e,:] = adj[i,j]!=0 ? (0,1) : (1,0),
// edge e -> (i = e/399, j = r + (r>=i)), r = e%399  (np.where(~eye) order).
//
// Output is batch-invariant: compute each tile ONCE in SMEM, then broadcast
// to all 32 batches via cp.async.bulk (UBLKCP shared->global). This removes
// all STG issue cost / LSU queue backpressure; the kernel becomes bounded by
// the chip-wide L2 write throughput (~6300 B/cyc -> ~3.2us for 40.85MB).

#define N_NODES 400
#define N_M1    399
#define N_EDGES 159600
#define E_PAIRS 79800           // float4 elements per batch
#define BATCH   32
#define TILE_F4 475             // float4s per tile (79800 / 168)
#define N_TILES 168
#define TILE_BYTES (TILE_F4 * 16)   // 7600, multiple of 16

__global__ __launch_bounds__(256)
void edge_onehot_tma_kernel(const float* __restrict__ adj, float4* __restrict__ out)
{
    __shared__ alignas(128) float4 buf[TILE_F4];

    const int tile = blockIdx.x;
    const int base_p = tile * TILE_F4;

    // Compute the tile once (475 float4 = 950 edges).
    for (int idx = threadIdx.x; idx < TILE_F4; idx += 256) {
        const int p  = base_p + idx;
        const int e0 = 2 * p;
        const int e1 = e0 + 1;

        int i0 = e0 / N_M1;
        int r0 = e0 - i0 * N_M1;
        int j0 = r0 + (r0 >= i0 ? 1 : 0);

        int i1 = e1 / N_M1;
        int r1 = e1 - i1 * N_M1;
        int j1 = r1 + (r1 >= i1 ? 1 : 0);

        const float a0 = __ldg(&adj[i0 * N_NODES + j0]);
        const float a1 = __ldg(&adj[i1 * N_NODES + j1]);

        const float t0 = (a0 != 0.0f) ? 1.0f : 0.0f;
        const float t1 = (a1 != 0.0f) ? 1.0f : 0.0f;

        float4 v;
        v.x = 1.0f - t0;
        v.y = t0;
        v.z = 1.0f - t1;
        v.w = t1;
        buf[idx] = v;
    }
    __syncthreads();

    // One thread broadcasts the tile to all 32 batch images via bulk async copy.
    if (threadIdx.x == 0) {
        // Order the generic-proxy SMEM writes before async-proxy reads.
        asm volatile("fence.proxy.async.shared::cta;" ::: "memory");

        uint32_t smem_addr;
        asm("{ .reg .u64 t; cvta.to.shared.u64 t, %1; cvt.u32.u64 %0, t; }"
            : "=r"(smem_addr) : "l"(buf));

#pragma unroll
        for (int b = 0; b < BATCH; ++b) {
            float4* dst = out + (size_t)b * E_PAIRS + base_p;
            asm volatile(
                "cp.async.bulk.global.shared::cta.bulk_group [%0], [%1], %2;"
                :: "l"(dst), "r"(smem_addr), "r"((uint32_t)TILE_BYTES)
                : "memory");
        }
        asm volatile("cp.async.bulk.commit_group;" ::: "memory");
        asm volatile("cp.async.bulk.wait_group 0;" ::: "memory");
    }
}

extern "C" void kernel_launch(void* const* d_in, const int* in_sizes, int n_in,
                              void* d_out, int out_size)
{
    // metadata order: inputs, weather, rel_rec, rel_send, adj_matrix
    const float* adj = (const float*)d_in[4];
    float4* out = (float4*)d_out;

    edge_onehot_tma_kernel<<<N_TILES, 256>>>(adj, out);
}

// round 5
// speedup vs baseline: 1.3488x; 1.3488x over previous
#include <cuda_runtime.h>
#include <cuda_bf16.h>
#include <cstdint>

// N = 400 nodes, E = N*(N-1) = 159600 edges, B = 32 batch.
// Output [B, E, 2] f32: out[b,e,:] = adj[i,j]!=0 ? (0,1) : (1,0),
// edge e -> (i = e/399, j = r + (r>=i)), r = e%399  (np.where(~eye) order).
//
// Batch-invariant output: each thread computes one float4 (2 edges) once and
// broadcasts it to BPT=16 batch images with streaming STG.128 (__stcs).
// Kernel is bounded by the LTS write path (~3000 B/cyc chip-wide -> ~6.5us
// floor for 40.85MB); this version minimizes redundant compute (2x) and
// store-train burstiness vs the BPT=8 variant.

#define N_NODES 400
#define N_M1    399
#define N_EDGES 159600
#define E_PAIRS 79800           // float4 elements per batch
#define BATCH   32
#define BPT     16              // batches per thread
#define GRID_Y  (BATCH / BPT)   // 2

__global__ __launch_bounds__(256)
void edge_onehot_bcast16_kernel(const float* __restrict__ adj, float4* __restrict__ out)
{
    const int p = blockIdx.x * blockDim.x + threadIdx.x;   // edge-pair index
    if (p >= E_PAIRS) return;

    const int e0 = 2 * p;
    const int e1 = e0 + 1;

    // edge -> (send i, rec j); /399 compiles to mul-hi+shift
    int i0 = e0 / N_M1;
    int r0 = e0 - i0 * N_M1;
    int j0 = r0 + (r0 >= i0 ? 1 : 0);

    int i1 = e1 / N_M1;
    int r1 = e1 - i1 * N_M1;
    int j1 = r1 + (r1 >= i1 ? 1 : 0);

    const float a0 = __ldg(&adj[i0 * N_NODES + j0]);
    const float a1 = __ldg(&adj[i1 * N_NODES + j1]);

    const float t0 = (a0 != 0.0f) ? 1.0f : 0.0f;
    const float t1 = (a1 != 0.0f) ? 1.0f : 0.0f;

    float4 v;
    v.x = 1.0f - t0;
    v.y = t0;
    v.z = 1.0f - t1;
    v.w = t1;

    // Broadcast to BPT batches, streaming (evict-first) stores.
    const int b0 = blockIdx.y * BPT;
    float4* dst = out + (size_t)b0 * E_PAIRS + p;
#pragma unroll
    for (int k = 0; k < BPT; ++k) {
        __stcs(dst + (size_t)k * E_PAIRS, v);
    }
}

extern "C" void kernel_launch(void* const* d_in, const int* in_sizes, int n_in,
                              void* d_out, int out_size)
{
    // metadata order: inputs, weather, rel_rec, rel_send, adj_matrix
    const float* adj = (const float*)d_in[4];
    float4* out = (float4*)d_out;

    dim3 block(256);
    dim3 grid((E_PAIRS + 255) / 256, GRID_Y);   // (312, 2)
    edge_onehot_bcast16_kernel<<<grid, block>>>(adj, out);
}

// round 7
// speedup vs baseline: 1.3851x; 1.0269x over previous
#include <cuda_runtime.h>
#include <cuda_bf16.h>
#include <cstdint>

// N = 400 nodes, E = N*(N-1) = 159600 edges, B = 32 batch.
// Output [B, E, 2] f32: out[b,e,:] = adj[i,j]!=0 ? (0,1) : (1,0),
// edge e -> (i = e/399, j = r + (r>=i)), r = e%399  (np.where(~eye) order).
//
// Batch-invariant output. Dual-path broadcast to exploit BOTH store engines:
//   - batches [0, NB_STG):  register STG.128 from every thread (LSU path)
//   - batches [NB_STG, 32): cp.async.bulk shared->global, one batch per
//     issuing thread with its own bulk group (async-engine path, parallel
//     issue — unlike the serialized single-thread variant that ran at
//     ~1800 B/cyc).
// Tile: 79800 float4 = 150 tiles x 532 float4 (8512 B smem) -> 150 CTAs,
// near-perfect balance on 148 SMs.

#define N_NODES 400
#define N_M1    399
#define E_PAIRS 79800           // float4 elements per batch
#define BATCH   32
#define TILE_F4 532
#define N_TILES 150             // 150 * 532 = 79800
#define TILE_BYTES (TILE_F4 * 16)   // 8512
#define NB_STG  12              // batches via STG
#define NB_BULK (BATCH - NB_STG)    // 20 batches via cp.async.bulk

__device__ __forceinline__ float4 compute_pair(int p)
{
    const int e0 = 2 * p;
    const int e1 = e0 + 1;
    int i0 = e0 / N_M1;
    int r0 = e0 - i0 * N_M1;
    int j0 = r0 + (r0 >= i0 ? 1 : 0);
    int i1 = e1 / N_M1;
    int r1 = e1 - i1 * N_M1;
    int j1 = r1 + (r1 >= i1 ? 1 : 0);
    return make_float4(0.f, 0.f, 0.f, 0.f); // placeholder, replaced below
}

__global__ __launch_bounds__(256)
void edge_onehot_dual_kernel(const float* __restrict__ adj, float4* __restrict__ out)
{
    __shared__ alignas(128) float4 buf[TILE_F4];

    const int tid = threadIdx.x;
    const int base_p = blockIdx.x * TILE_F4;

    // ---- Phase 1: compute tile once; keep values in regs AND mirror to smem.
    float4 v0, v1, v2;
    {
        const int p = base_p + tid;                 // slot 0: tid in [0,256)
        const int e0 = 2 * p, e1 = e0 + 1;
        int i0 = e0 / N_M1, r0 = e0 - i0 * N_M1;
        int j0 = r0 + (r0 >= i0 ? 1 : 0);
        int i1 = e1 / N_M1, r1 = e1 - i1 * N_M1;
        int j1 = r1 + (r1 >= i1 ? 1 : 0);
        float t0 = (__ldg(&adj[i0 * N_NODES + j0]) != 0.0f) ? 1.0f : 0.0f;
        float t1 = (__ldg(&adj[i1 * N_NODES + j1]) != 0.0f) ? 1.0f : 0.0f;
        v0 = make_float4(1.0f - t0, t0, 1.0f - t1, t1);
        buf[tid] = v0;
    }
    {
        const int idx = tid + 256;                  // slot 1: [256,512)
        const int p = base_p + idx;
        const int e0 = 2 * p, e1 = e0 + 1;
        int i0 = e0 / N_M1, r0 = e0 - i0 * N_M1;
        int j0 = r0 + (r0 >= i0 ? 1 : 0);
        int i1 = e1 / N_M1, r1 = e1 - i1 * N_M1;
        int j1 = r1 + (r1 >= i1 ? 1 : 0);
        float t0 = (__ldg(&adj[i0 * N_NODES + j0]) != 0.0f) ? 1.0f : 0.0f;
        float t1 = (__ldg(&adj[i1 * N_NODES + j1]) != 0.0f) ? 1.0f : 0.0f;
        v1 = make_float4(1.0f - t0, t0, 1.0f - t1, t1);
        buf[idx] = v1;
    }
    const bool has2 = (tid < TILE_F4 - 512);        // 20 threads: [512,532)
    if (has2) {
        const int idx = tid + 512;
        const int p = base_p + idx;
        const int e0 = 2 * p, e1 = e0 + 1;
        int i0 = e0 / N_M1, r0 = e0 - i0 * N_M1;
        int j0 = r0 + (r0 >= i0 ? 1 : 0);
        int i1 = e1 / N_M1, r1 = e1 - i1 * N_M1;
        int j1 = r1 + (r1 >= i1 ? 1 : 0);
        float t0 = (__ldg(&adj[i0 * N_NODES + j0]) != 0.0f) ? 1.0f : 0.0f;
        float t1 = (__ldg(&adj[i1 * N_NODES + j1]) != 0.0f) ? 1.0f : 0.0f;
        v2 = make_float4(1.0f - t0, t0, 1.0f - t1, t1);
        buf[idx] = v2;
    }

    __syncthreads();

    // ---- Phase 2a: async-engine path. Threads 0..NB_BULK-1 each broadcast
    // the smem tile to one batch image with their own bulk group.
    if (tid < NB_BULK) {
        asm volatile("fence.proxy.async.shared::cta;" ::: "memory");
        uint32_t smem_addr;
        asm("{ .reg .u64 t; cvta.to.shared.u64 t, %1; cvt.u32.u64 %0, t; }"
            : "=r"(smem_addr) : "l"(buf));
        const int b = NB_STG + tid;
        float4* dst = out + (size_t)b * E_PAIRS + base_p;
        asm volatile(
            "cp.async.bulk.global.shared::cta.bulk_group [%0], [%1], %2;"
            :: "l"(dst), "r"(smem_addr), "r"((uint32_t)TILE_BYTES)
            : "memory");
        asm volatile("cp.async.bulk.commit_group;" ::: "memory");
    }

    // ---- Phase 2b: LSU path. All threads store their register values to
    // batches [0, NB_STG) with streaming STG.128.
    float4* base0 = out + base_p + tid;
#pragma unroll
    for (int b = 0; b < NB_STG; ++b) {
        float4* d = base0 + (size_t)b * E_PAIRS;
        __stcs(d, v0);
        __stcs(d + 256, v1);
        if (has2) __stcs(d + 512, v2);
    }

    // ---- Drain bulk copies before CTA exit (smem lifetime).
    if (tid < NB_BULK) {
        asm volatile("cp.async.bulk.wait_group 0;" ::: "memory");
    }
    __syncthreads();
}

extern "C" void kernel_launch(void* const* d_in, const int* in_sizes, int n_in,
                              void* d_out, int out_size)
{
    // metadata order: inputs, weather, rel_rec, rel_send, adj_matrix
    const float* adj = (const float*)d_in[4];
    float4* out = (float4*)d_out;

    edge_onehot_dual_kernel<<<N_TILES, 256>>>(adj, out);
}